// round 16
// baseline (speedup 1.0000x reference)
#include <cuda_runtime.h>
#include <stdint.h>
#include <math.h>

#define BB   64
#define CC   512
#define HW   784
#define NREG 64
#define TT   56
#define NTILE 14
#define GT   448
// X layout: 16B unit u = tp*257 + k2  (tp = pixel pair 0..27, k2 = K pair 0..255)
// float idx = 4u + (t&1)*2 + (c&1).
// Prefetch overrun bound: worst read is pair 27, k2=256, +1 unit ->
// fidx (27*257+256)*4 + 4 .. +7 = 28784..28787. Pad to 28800.
#define XS_FLOATS 28800
#define XS_BYTES  (XS_FLOATS*4)
#define OFF14     (14*257*4)

// ---------------- scratch ----------------
__device__ __align__(256) float g_scale[CC];
__device__ __align__(256) float g_shift[CC];
__device__ __align__(256) float g_rowsum[BB*CC];
__device__ __align__(256) float g_rowsq [BB*CC];
__device__ __align__(256) float g_a1   [BB*CC];
__device__ __align__(256) float g_pooled[BB*CC];
__device__ __align__(256) float g_att2 [BB*HW];
__device__ __align__(256) float g_srean[(size_t)BB*NREG*HW];
__device__ __align__(256) float g_scorep[BB*NTILE*NREG];
__device__ __align__(256) float g_l3[BB];
__device__ __align__(256) float g_ls[BB];

// ---------------- helpers ----------------
__device__ __forceinline__ float wredsum(float v){
    #pragma unroll
    for (int o = 16; o; o >>= 1) v += __shfl_down_sync(0xffffffffu, v, o);
    return v;
}
__device__ __forceinline__ float wredmax(float v){
    #pragma unroll
    for (int o = 16; o; o >>= 1) v = fmaxf(v, __shfl_down_sync(0xffffffffu, v, o));
    return v;
}
__device__ __forceinline__ float blockRedSum256(float v, float* red){
    int lane = threadIdx.x & 31, w = threadIdx.x >> 5;
    v = wredsum(v);
    if (lane == 0) red[w] = v;
    __syncthreads();
    if (threadIdx.x == 0){
        float s = 0.f;
        #pragma unroll
        for (int i = 0; i < 8; i++) s += red[i];
        red[0] = s;
    }
    __syncthreads();
    float r = red[0];
    __syncthreads();
    return r;
}
__device__ __forceinline__ float blockRedMax256(float v, float* red){
    int lane = threadIdx.x & 31, w = threadIdx.x >> 5;
    v = wredmax(v);
    if (lane == 0) red[w] = v;
    __syncthreads();
    if (threadIdx.x == 0){
        float s = red[0];
        #pragma unroll
        for (int i = 1; i < 8; i++) s = fmaxf(s, red[i]);
        red[0] = s;
    }
    __syncthreads();
    float r = red[0];
    __syncthreads();
    return r;
}

#define FMA2(d,a,b) asm("fma.rn.f32x2 %0, %1, %2, %0;" : "+l"(d) : "l"(a), "l"(b))
__device__ __forceinline__ float2 up2(unsigned long long v){
    float2 r; asm("mov.b64 {%0, %1}, %2;" : "=f"(r.x), "=f"(r.y) : "l"(v)); return r;
}
__device__ __forceinline__ int lidx(int c, int t){
    return (((t>>1)*257 + (c>>1))<<2) + ((t&1)<<1) + (c&1);
}
__device__ __forceinline__ void stcs2(float* p, float2 v){
    asm volatile("st.global.cs.v2.f32 [%0], {%1, %2};" :: "l"(p), "f"(v.x), "f"(v.y) : "memory");
}

// ---------------- K1a: per-(b,c) row sums ----------------
__global__ void k_rowsum(const float* __restrict__ v){
    int w = (blockIdx.x * blockDim.x + threadIdx.x) >> 5;
    int lane = threadIdx.x & 31;
    if (w >= BB*CC) return;
    const float4* row = (const float4*)(v + (size_t)w * HW);
    float p = 0.f, q = 0.f;
    #pragma unroll
    for (int i = 0; i < 7; i++){
        int idx = lane + i*32;
        if (idx < 196){
            float4 x = row[idx];
            p += x.x + x.y + x.z + x.w;
            q += x.x*x.x + x.y*x.y + x.z*x.z + x.w*x.w;
        }
    }
    p = wredsum(p); q = wredsum(q);
    if (lane == 0){ g_rowsum[w] = p; g_rowsq[w] = q; }
}

// ---------------- K1b: BN params + pooled (blocks 0..511); a1 l2norm (512..575) ----------------
__global__ void k_prep(const float* __restrict__ gamma, const float* __restrict__ beta,
                       const float* __restrict__ t){
    int tid = threadIdx.x;  // 128
    if (blockIdx.x < CC){
        int c = blockIdx.x;
        __shared__ float sp[BB], sq[BB];
        __shared__ float ssc, ssh;
        if (tid < BB){
            sp[tid] = g_rowsum[tid*CC + c];
            sq[tid] = g_rowsq [tid*CC + c];
        }
        __syncthreads();
        if (tid == 0){
            float P = 0.f, Q = 0.f;
            for (int i = 0; i < BB; i++){ P += sp[i]; Q += sq[i]; }
            const float inv = 1.0f / (float)(BB*HW);
            float mu  = P * inv;
            float var = Q * inv - mu*mu;
            float sc  = gamma[c] * rsqrtf(var + 1e-5f);
            float sh  = beta[c] - mu * sc;
            g_scale[c] = sc;
            g_shift[c] = sh;
            ssc = sc; ssh = sh;
        }
        __syncthreads();
        if (tid < BB)
            g_pooled[tid*CC + c] = sp[tid] * (1.0f/(float)HW) * ssc + ssh;
    } else {
        int b = blockIdx.x - CC;
        float s = 0.f;
        for (int c = tid; c < CC; c += 128){ float x = t[b*CC + c]; s += x*x; }
        __shared__ float red[4];
        __shared__ float sinv;
        float ws = wredsum(s);
        if ((tid & 31) == 0) red[tid >> 5] = ws;
        __syncthreads();
        if (tid == 0) sinv = 1.0f / fmaxf(sqrtf(red[0]+red[1]+red[2]+red[3]), 1e-12f);
        __syncthreads();
        for (int c = tid; c < CC; c += 128) g_a1[b*CC + c] = t[b*CC + c] * sinv;
    }
}

// ---------------- K3: fused main pass (round-8 proven version) ----------------
__global__ void __launch_bounds__(GT) k_main(
    const float* __restrict__ v,
    const float* __restrict__ w,
    const float* __restrict__ wb)
{
    extern __shared__ float Xs[];
    __shared__ float pr[8*TT], pa[8*TT], satt[TT], sinv[TT];
    __shared__ float pn[8*TT];
    __shared__ float stile[NREG*NTILE];

    int b    = blockIdx.x / NTILE;
    int tile = blockIdx.x % NTILE;
    int hw0  = tile * TT;
    int tid  = threadIdx.x;

    // ---- fill Xs + fused norm/att partials ----
    {
        int t  = tid % TT;
        int c0 = tid / TT;                  // 0..7
        const float* base = v + (size_t)b*CC*HW + hw0 + t;
        const float* a1b  = g_a1 + b*CC;
        float nr = 0.f, ad = 0.f;
        int fx = lidx(c0, t);
        #pragma unroll 8
        for (int c = c0; c < CC; c += 8){
            float x = base[(size_t)c*HW] * g_scale[c] + g_shift[c];
            Xs[fx] = x;
            fx += 16;
            nr = fmaf(x, x, nr);
            ad = fmaf(x, a1b[c], ad);
        }
        pr[c0*TT + t] = nr;
        pa[c0*TT + t] = ad;
    }
    __syncthreads();
    if (tid < TT){
        float nr = 0.f, ad = 0.f;
        #pragma unroll
        for (int s = 0; s < 8; s++){ nr += pr[s*TT + tid]; ad += pa[s*TT + tid]; }
        float a = ad / fmaxf(sqrtf(nr), 1e-12f);
        satt[tid] = a;
        g_att2[b*HW + hw0 + tid] = a;
    }

    // ---- GEMM: kq=tid/112, r=tid%112, tn=r/14 (8 n-rows), tt=r%14 (px pairs tt, tt+14) ----
    int kq = tid / 112;
    int r  = tid % 112;
    int tn = r / NTILE;
    int tt = r % NTILE;
    int n0 = tn*8;
    int p0 = 2*tt;

    unsigned long long acc[8][4];
    #pragma unroll
    for (int i = 0; i < 8; i++)
        #pragma unroll
        for (int j = 0; j < 4; j++) acc[i][j] = 0ull;

    {
        const ulonglong2* wp = (const ulonglong2*)w + n0*128 + kq*32;
        int s = (tt*257 + kq*64) << 2;

        // software pipeline: preload iter-0 X
        ulonglong2 xa0 = *(const ulonglong2*)(Xs + s);
        ulonglong2 xa1 = *(const ulonglong2*)(Xs + s + 4);
        ulonglong2 xb0 = *(const ulonglong2*)(Xs + s + OFF14);
        ulonglong2 xb1 = *(const ulonglong2*)(Xs + s + OFF14 + 4);

        #pragma unroll 1
        for (int k4 = 0; k4 < 32; k4++){
            s += 8;
            // prefetch next iteration's X (padding covers last-iter overrun)
            ulonglong2 na0 = *(const ulonglong2*)(Xs + s);
            ulonglong2 na1 = *(const ulonglong2*)(Xs + s + 4);
            ulonglong2 nb0 = *(const ulonglong2*)(Xs + s + OFF14);
            ulonglong2 nb1 = *(const ulonglong2*)(Xs + s + OFF14 + 4);

            {
                ulonglong2 wv0 = wp[k4 + 0*128];
                ulonglong2 wv1 = wp[k4 + 1*128];
                ulonglong2 wv2 = wp[k4 + 2*128];
                ulonglong2 wv3 = wp[k4 + 3*128];
                FMA2(acc[0][0], wv0.x, xa0.x); FMA2(acc[0][1], wv0.x, xa0.y);
                FMA2(acc[0][2], wv0.x, xb0.x); FMA2(acc[0][3], wv0.x, xb0.y);
                FMA2(acc[0][0], wv0.y, xa1.x); FMA2(acc[0][1], wv0.y, xa1.y);
                FMA2(acc[0][2], wv0.y, xb1.x); FMA2(acc[0][3], wv0.y, xb1.y);
                FMA2(acc[1][0], wv1.x, xa0.x); FMA2(acc[1][1], wv1.x, xa0.y);
                FMA2(acc[1][2], wv1.x, xb0.x); FMA2(acc[1][3], wv1.x, xb0.y);
                FMA2(acc[1][0], wv1.y, xa1.x); FMA2(acc[1][1], wv1.y, xa1.y);
                FMA2(acc[1][2], wv1.y, xb1.x); FMA2(acc[1][3], wv1.y, xb1.y);
                FMA2(acc[2][0], wv2.x, xa0.x); FMA2(acc[2][1], wv2.x, xa0.y);
                FMA2(acc[2][2], wv2.x, xb0.x); FMA2(acc[2][3], wv2.x, xb0.y);
                FMA2(acc[2][0], wv2.y, xa1.x); FMA2(acc[2][1], wv2.y, xa1.y);
                FMA2(acc[2][2], wv2.y, xb1.x); FMA2(acc[2][3], wv2.y, xb1.y);
                FMA2(acc[3][0], wv3.x, xa0.x); FMA2(acc[3][1], wv3.x, xa0.y);
                FMA2(acc[3][2], wv3.x, xb0.x); FMA2(acc[3][3], wv3.x, xb0.y);
                FMA2(acc[3][0], wv3.y, xa1.x); FMA2(acc[3][1], wv3.y, xa1.y);
                FMA2(acc[3][2], wv3.y, xb1.x); FMA2(acc[3][3], wv3.y, xb1.y);
            }
            {
                ulonglong2 wv4 = wp[k4 + 4*128];
                ulonglong2 wv5 = wp[k4 + 5*128];
                ulonglong2 wv6 = wp[k4 + 6*128];
                ulonglong2 wv7 = wp[k4 + 7*128];
                FMA2(acc[4][0], wv4.x, xa0.x); FMA2(acc[4][1], wv4.x, xa0.y);
                FMA2(acc[4][2], wv4.x, xb0.x); FMA2(acc[4][3], wv4.x, xb0.y);
                FMA2(acc[4][0], wv4.y, xa1.x); FMA2(acc[4][1], wv4.y, xa1.y);
                FMA2(acc[4][2], wv4.y, xb1.x); FMA2(acc[4][3], wv4.y, xb1.y);
                FMA2(acc[5][0], wv5.x, xa0.x); FMA2(acc[5][1], wv5.x, xa0.y);
                FMA2(acc[5][2], wv5.x, xb0.x); FMA2(acc[5][3], wv5.x, xb0.y);
                FMA2(acc[5][0], wv5.y, xa1.x); FMA2(acc[5][1], wv5.y, xa1.y);
                FMA2(acc[5][2], wv5.y, xb1.x); FMA2(acc[5][3], wv5.y, xb1.y);
                FMA2(acc[6][0], wv6.x, xa0.x); FMA2(acc[6][1], wv6.x, xa0.y);
                FMA2(acc[6][2], wv6.x, xb0.x); FMA2(acc[6][3], wv6.x, xb0.y);
                FMA2(acc[6][0], wv6.y, xa1.x); FMA2(acc[6][1], wv6.y, xa1.y);
                FMA2(acc[6][2], wv6.y, xb1.x); FMA2(acc[6][3], wv6.y, xb1.y);
                FMA2(acc[7][0], wv7.x, xa0.x); FMA2(acc[7][1], wv7.x, xa0.y);
                FMA2(acc[7][2], wv7.x, xb0.x); FMA2(acc[7][3], wv7.x, xb0.y);
                FMA2(acc[7][0], wv7.y, xa1.x); FMA2(acc[7][1], wv7.y, xa1.y);
                FMA2(acc[7][2], wv7.y, xb1.x); FMA2(acc[7][3], wv7.y, xb1.y);
            }
            xa0 = na0; xa1 = na1; xb0 = nb0; xb1 = nb1;
        }
    }

    // ---- combine K quarters, normalize, store ----
    __syncthreads();
    float* comb = Xs;

    float sres[8][4];
    #pragma unroll
    for (int i = 0; i < 8; i++)
        #pragma unroll
        for (int j = 0; j < 4; j++){
            float2 f = up2(acc[i][j]);
            sres[i][j] = f.x + f.y;
        }

    if (kq){
        float* cb = comb + (kq-1)*NREG*TT;
        #pragma unroll
        for (int i = 0; i < 8; i++){
            int rw = (n0+i)*TT;
            *(float2*)&cb[rw + p0]      = make_float2(sres[i][0], sres[i][1]);
            *(float2*)&cb[rw + p0 + 28] = make_float2(sres[i][2], sres[i][3]);
        }
    }
    __syncthreads();
    if (kq == 0){
        #pragma unroll
        for (int i = 0; i < 8; i++){
            float bi = wb[n0+i];
            int rw = (n0+i)*TT;
            sres[i][0] += comb[rw+p0]    + comb[NREG*TT + rw+p0]    + comb[2*NREG*TT + rw+p0]    + bi;
            sres[i][1] += comb[rw+p0+1]  + comb[NREG*TT + rw+p0+1]  + comb[2*NREG*TT + rw+p0+1]  + bi;
            sres[i][2] += comb[rw+p0+28] + comb[NREG*TT + rw+p0+28] + comb[2*NREG*TT + rw+p0+28] + bi;
            sres[i][3] += comb[rw+p0+29] + comb[NREG*TT + rw+p0+29] + comb[2*NREG*TT + rw+p0+29] + bi;
        }
        float ss0 = 0.f, ss1 = 0.f, ss2 = 0.f, ss3 = 0.f;
        #pragma unroll
        for (int i = 0; i < 8; i++){
            ss0 = fmaf(sres[i][0], sres[i][0], ss0);
            ss1 = fmaf(sres[i][1], sres[i][1], ss1);
            ss2 = fmaf(sres[i][2], sres[i][2], ss2);
            ss3 = fmaf(sres[i][3], sres[i][3], ss3);
        }
        *(float2*)&pn[tn*TT + p0]      = make_float2(ss0, ss1);
        *(float2*)&pn[tn*TT + p0 + 28] = make_float2(ss2, ss3);
    }
    __syncthreads();
    if (tid < TT){
        float ss = 0.f;
        #pragma unroll
        for (int g = 0; g < 8; g++) ss += pn[g*TT + tid];
        sinv[tid] = 1.0f / fmaxf(sqrtf(ss), 1e-12f);
    }
    __syncthreads();
    if (kq == 0){
        float* outb = g_srean + ((size_t)b*NREG)*HW + hw0;
        float a0 = satt[p0], a1v = satt[p0+1], a2 = satt[p0+28], a3 = satt[p0+29];
        float i0 = sinv[p0], i1 = sinv[p0+1], i2 = sinv[p0+28], i3 = sinv[p0+29];
        #pragma unroll
        for (int i = 0; i < 8; i++){
            float o0 = sres[i][0]*i0, o1 = sres[i][1]*i1;
            float o2 = sres[i][2]*i2, o3 = sres[i][3]*i3;
            float* orow = outb + (size_t)(n0+i)*HW;
            stcs2(&orow[p0],      make_float2(o0, o1));
            stcs2(&orow[p0 + 28], make_float2(o2, o3));
            stile[(n0+i)*NTILE + tt] = o0*a0 + o1*a1v + o2*a2 + o3*a3;
        }
    }
    __syncthreads();
    if (tid < NREG){
        float q = 0.f;
        #pragma unroll
        for (int tl = 0; tl < NTILE; tl++) q += stile[tid*NTILE + tl];
        g_scorep[(b*NTILE + tile)*NREG + tid] = q;
    }
}

// ---------------- K6: loss (blocks 0..63) + feat+dual_sim (blocks 64..127) ----------------
__global__ void k_lossdual(const float* __restrict__ fw, const float* __restrict__ fb,
                           float* __restrict__ out){
    int tid = threadIdx.x;  // 256
    if (blockIdx.x < BB){
        int b = blockIdx.x;
        __shared__ float ssc[NREG];
        __shared__ int s_nmax;
        __shared__ float red[8];
        if (tid < NREG){
            float sv = 0.f;
            #pragma unroll
            for (int tl = 0; tl < NTILE; tl++) sv += g_scorep[(b*NTILE + tl)*NREG + tid];
            ssc[tid] = sv;
        }
        __syncthreads();
        if (tid == 0){
            float m = 0.f;
            for (int n = 0; n < NREG; n++) m += ssc[n];
            m *= (1.0f/NREG);
            float bmax = ssc[0]; int imax = 0;
            float sp = 0.f, sq = 0.f;
            for (int n = 0; n < NREG; n++){
                float x = ssc[n];
                if (x > bmax){ bmax = x; imax = n; }
                if (x > m) sp += x; else sq += x;
            }
            sp *= (1.0f/NREG); sq *= (1.0f/NREG);
            float d = sq - sp;
            g_l3[b] = (d > 20.0f) ? d : log1pf(expf(d));
            s_nmax = imax;
        }
        __syncthreads();

        const float* pl = g_att2 + b*HW;
        const float* ql = g_srean + ((size_t)b*NREG + s_nmax)*HW;
        const float qs = 1.0f/(float)NREG;

        float mp = -1e30f, mq = -1e30f;
        for (int h = tid; h < HW; h += 256){
            mp = fmaxf(mp, pl[h]);
            mq = fmaxf(mq, ql[h]*qs);
        }
        mp = blockRedMax256(mp, red);
        mq = blockRedMax256(mq, red);

        float ep = 0.f, eq = 0.f;
        for (int h = tid; h < HW; h += 256){
            ep += expf(pl[h] - mp);
            eq += expf(ql[h]*qs - mq);
        }
        ep = blockRedSum256(ep, red);
        eq = blockRedSum256(eq, red);
        float lsep = mp + logf(ep);
        float lseq = mq + logf(eq);

        float S = 0.f;
        for (int h = tid; h < HW; h += 256){
            float lp = pl[h] - lsep;
            float lq = ql[h]*qs - lseq;
            float p  = expf(lp);
            float q  = expf(lq);
            float lm = logf(0.5f*(p + q));
            S += p*(lp - lm) + q*(lq - lm);
        }
        S = blockRedSum256(S, red);
        if (tid == 0) g_ls[b] = S;
    } else {
        int b = blockIdx.x - BB;
        __shared__ __align__(16) float ps[CC];
        __shared__ __align__(16) float fr[CC];
        __shared__ float red[8];
        __shared__ float sinvb;

        for (int c = tid; c < CC; c += 256) ps[c] = g_pooled[b*CC + c];
        __syncthreads();

        // feat[c] = pooled[b] . fw[c,:] + fb[c]  (each thread: c = tid, tid+256)
        float ss = 0.f;
        #pragma unroll
        for (int h = 0; h < 2; h++){
            int c = tid + h*256;
            const float4* wr = (const float4*)(fw + (size_t)c*CC);
            float4 s4 = make_float4(0.f, 0.f, 0.f, 0.f);
            #pragma unroll 8
            for (int k4 = 0; k4 < CC/4; k4++){
                float4 wv = wr[k4];
                float4 pv = *(const float4*)&ps[k4*4];
                s4.x = fmaf(wv.x, pv.x, s4.x);
                s4.y = fmaf(wv.y, pv.y, s4.y);
                s4.z = fmaf(wv.z, pv.z, s4.z);
                s4.w = fmaf(wv.w, pv.w, s4.w);
            }
            float x = (s4.x + s4.y) + (s4.z + s4.w) + fb[c];
            fr[c] = x;
            ss += x*x;
        }
        ss = blockRedSum256(ss, red);
        if (tid == 0) sinvb = 1.0f / fmaxf(sqrtf(ss), 1e-12f);
        __syncthreads();
        int warp = tid >> 5, lane = tid & 31;
        for (int j = warp; j < BB; j += 8){
            const float* a = g_a1 + j*CC;
            float s = 0.f;
            for (int c = lane; c < CC; c += 32) s += fr[c] * a[c];
            s = wredsum(s);
            if (lane == 0) out[b*BB + j] = s * sinvb;
        }
    }
}

// ---------------- K8: final scalar ----------------
__global__ void k_final(float* __restrict__ out, int li){
    int t = threadIdx.x;  // 64
    __shared__ float r3[BB], rls[BB];
    r3[t] = g_l3[t]; rls[t] = g_ls[t];
    __syncthreads();
    if (t == 0){
        float a = 0.f, c2 = 0.f;
        for (int i = 0; i < BB; i++){ a += r3[i]; c2 += rls[i]; }
        float loss3 = a / (float)BB;
        float loss2 = 0.5f * c2 / (float)BB;
        out[li] = 0.1f*loss3 + 0.1f*loss2;
    }
}

// ---------------- launcher ----------------
extern "C" void kernel_launch(void* const* d_in, const int* in_sizes, int n_in,
                              void* d_out, int out_size){
    const float* v     = (const float*)d_in[0];
    const float* t     = (const float*)d_in[1];
    const float* cw    = (const float*)d_in[2];
    const float* cb    = (const float*)d_in[3];
    const float* gamma = (const float*)d_in[4];
    const float* beta  = (const float*)d_in[5];
    const float* fw    = (const float*)d_in[6];
    const float* fb    = (const float*)d_in[7];
    float* out = (float*)d_out;

    cudaFuncSetAttribute(k_main, cudaFuncAttributeMaxDynamicSharedMemorySize, XS_BYTES);

    k_rowsum<<<(BB*CC)/8, 256>>>(v);
    k_prep<<<CC + BB, 128>>>(gamma, beta, t);
    k_main<<<BB*NTILE, GT, XS_BYTES>>>(v, cw, cb);
    k_lossdual<<<2*BB, 256>>>(fw, fb, out);
    int li = (out_size > 4096) ? 4096 : (out_size - 1);
    k_final<<<1, 64>>>(out, li);
}

// round 17
// speedup vs baseline: 1.1105x; 1.1105x over previous
#include <cuda_runtime.h>
#include <stdint.h>
#include <math.h>

#define BB   64
#define CC   512
#define HW   784
#define NREG 64
#define TT   56
#define NTILE 14
#define GT   448
// X layout: 16B unit u = tp*257 + k2  (tp = pixel pair 0..27, k2 = K pair 0..255)
// float idx = 4u + (t&1)*2 + (c&1).
// Prefetch overrun bound: worst read is pair 27, k2=256, +1 unit ->
// fidx (27*257+256)*4 + 4 .. +7 = 28784..28787. Pad to 28800.
#define XS_FLOATS 28800
#define XS_BYTES  (XS_FLOATS*4)
#define OFF14     (14*257*4)

// ---------------- scratch ----------------
__device__ __align__(256) float g_scale[CC];
__device__ __align__(256) float g_shift[CC];
__device__ __align__(256) float g_rowsum[BB*CC];
__device__ __align__(256) float g_rowsq [BB*CC];
__device__ __align__(256) float g_a1   [BB*CC];
__device__ __align__(256) float g_pooled[BB*CC];
__device__ __align__(256) float g_att2 [BB*HW];
__device__ __align__(256) float g_srean[(size_t)BB*NREG*HW];
__device__ __align__(256) float g_scorep[BB*NTILE*NREG];
__device__ __align__(256) float g_featp[4*BB*CC];
__device__ __align__(256) float g_l3[BB];
__device__ __align__(256) float g_ls[BB];

// ---------------- helpers ----------------
__device__ __forceinline__ float wredsum(float v){
    #pragma unroll
    for (int o = 16; o; o >>= 1) v += __shfl_down_sync(0xffffffffu, v, o);
    return v;
}
__device__ __forceinline__ float wredmax(float v){
    #pragma unroll
    for (int o = 16; o; o >>= 1) v = fmaxf(v, __shfl_down_sync(0xffffffffu, v, o));
    return v;
}
__device__ __forceinline__ float blockRedSum256(float v, float* red){
    int lane = threadIdx.x & 31, w = threadIdx.x >> 5;
    v = wredsum(v);
    if (lane == 0) red[w] = v;
    __syncthreads();
    if (threadIdx.x == 0){
        float s = 0.f;
        #pragma unroll
        for (int i = 0; i < 8; i++) s += red[i];
        red[0] = s;
    }
    __syncthreads();
    float r = red[0];
    __syncthreads();
    return r;
}
__device__ __forceinline__ float blockRedMax256(float v, float* red){
    int lane = threadIdx.x & 31, w = threadIdx.x >> 5;
    v = wredmax(v);
    if (lane == 0) red[w] = v;
    __syncthreads();
    if (threadIdx.x == 0){
        float s = red[0];
        #pragma unroll
        for (int i = 1; i < 8; i++) s = fmaxf(s, red[i]);
        red[0] = s;
    }
    __syncthreads();
    float r = red[0];
    __syncthreads();
    return r;
}

#define FMA2(d,a,b) asm("fma.rn.f32x2 %0, %1, %2, %0;" : "+l"(d) : "l"(a), "l"(b))
__device__ __forceinline__ float2 up2(unsigned long long v){
    float2 r; asm("mov.b64 {%0, %1}, %2;" : "=f"(r.x), "=f"(r.y) : "l"(v)); return r;
}
__device__ __forceinline__ int lidx(int c, int t){
    return (((t>>1)*257 + (c>>1))<<2) + ((t&1)<<1) + (c&1);
}
__device__ __forceinline__ void stcs2(float* p, float2 v){
    asm volatile("st.global.cs.v2.f32 [%0], {%1, %2};" :: "l"(p), "f"(v.x), "f"(v.y) : "memory");
}

// ---------------- K1a: per-(b,c) row sums ----------------
__global__ void k_rowsum(const float* __restrict__ v){
    int w = (blockIdx.x * blockDim.x + threadIdx.x) >> 5;
    int lane = threadIdx.x & 31;
    if (w >= BB*CC) return;
    const float4* row = (const float4*)(v + (size_t)w * HW);
    float p = 0.f, q = 0.f;
    #pragma unroll
    for (int i = 0; i < 7; i++){
        int idx = lane + i*32;
        if (idx < 196){
            float4 x = row[idx];
            p += x.x + x.y + x.z + x.w;
            q += x.x*x.x + x.y*x.y + x.z*x.z + x.w*x.w;
        }
    }
    p = wredsum(p); q = wredsum(q);
    if (lane == 0){ g_rowsum[w] = p; g_rowsq[w] = q; }
}

// ---------------- K1b: BN params + pooled (blocks 0..511); a1 l2norm (512..575) ----------------
__global__ void k_prep(const float* __restrict__ gamma, const float* __restrict__ beta,
                       const float* __restrict__ t){
    int tid = threadIdx.x;  // 128
    if (blockIdx.x < CC){
        int c = blockIdx.x;
        __shared__ float sp[BB], sq[BB];
        __shared__ float ssc, ssh;
        if (tid < BB){
            sp[tid] = g_rowsum[tid*CC + c];
            sq[tid] = g_rowsq [tid*CC + c];
        }
        __syncthreads();
        if (tid == 0){
            float P = 0.f, Q = 0.f;
            for (int i = 0; i < BB; i++){ P += sp[i]; Q += sq[i]; }
            const float inv = 1.0f / (float)(BB*HW);
            float mu  = P * inv;
            float var = Q * inv - mu*mu;
            float sc  = gamma[c] * rsqrtf(var + 1e-5f);
            float sh  = beta[c] - mu * sc;
            g_scale[c] = sc;
            g_shift[c] = sh;
            ssc = sc; ssh = sh;
        }
        __syncthreads();
        if (tid < BB)
            g_pooled[tid*CC + c] = sp[tid] * (1.0f/(float)HW) * ssc + ssh;
    } else {
        int b = blockIdx.x - CC;
        float s = 0.f;
        for (int c = tid; c < CC; c += 128){ float x = t[b*CC + c]; s += x*x; }
        __shared__ float red[4];
        __shared__ float sinv;
        float ws = wredsum(s);
        if ((tid & 31) == 0) red[tid >> 5] = ws;
        __syncthreads();
        if (tid == 0) sinv = 1.0f / fmaxf(sqrtf(red[0]+red[1]+red[2]+red[3]), 1e-12f);
        __syncthreads();
        for (int c = tid; c < CC; c += 128) g_a1[b*CC + c] = t[b*CC + c] * sinv;
    }
}

// ---------------- K3: fused main pass (round-8 GEMM + parallelized epilogue) ----------------
__global__ void __launch_bounds__(GT) k_main(
    const float* __restrict__ v,
    const float* __restrict__ w,
    const float* __restrict__ wb)
{
    extern __shared__ float Xs[];
    __shared__ float pr[8*TT], pa[8*TT], satt[TT], sinv[TT];
    __shared__ float pn[32*TT];
    __shared__ float stile[NREG*NTILE];

    int b    = blockIdx.x / NTILE;
    int tile = blockIdx.x % NTILE;
    int hw0  = tile * TT;
    int tid  = threadIdx.x;

    // ---- fill Xs + fused norm/att partials ----
    {
        int t  = tid % TT;
        int c0 = tid / TT;                  // 0..7
        const float* base = v + (size_t)b*CC*HW + hw0 + t;
        const float* a1b  = g_a1 + b*CC;
        float nr = 0.f, ad = 0.f;
        int fx = lidx(c0, t);
        #pragma unroll 8
        for (int c = c0; c < CC; c += 8){
            float x = base[(size_t)c*HW] * g_scale[c] + g_shift[c];
            Xs[fx] = x;
            fx += 16;
            nr = fmaf(x, x, nr);
            ad = fmaf(x, a1b[c], ad);
        }
        pr[c0*TT + t] = nr;
        pa[c0*TT + t] = ad;
    }
    __syncthreads();
    if (tid < TT){
        float nr = 0.f, ad = 0.f;
        #pragma unroll
        for (int s = 0; s < 8; s++){ nr += pr[s*TT + tid]; ad += pa[s*TT + tid]; }
        float a = ad / fmaxf(sqrtf(nr), 1e-12f);
        satt[tid] = a;
        g_att2[b*HW + hw0 + tid] = a;
    }

    // ---- GEMM: kq=tid/112, r=tid%112, tn=r/14 (8 n-rows), tt=r%14 (px pairs tt, tt+14) ----
    int kq = tid / 112;
    int r  = tid % 112;
    int tn = r / NTILE;
    int tt = r % NTILE;
    int n0 = tn*8;
    int p0 = 2*tt;

    unsigned long long acc[8][4];
    #pragma unroll
    for (int i = 0; i < 8; i++)
        #pragma unroll
        for (int j = 0; j < 4; j++) acc[i][j] = 0ull;

    {
        const ulonglong2* wp = (const ulonglong2*)w + n0*128 + kq*32;
        int s = (tt*257 + kq*64) << 2;

        // software pipeline: preload iter-0 X
        ulonglong2 xa0 = *(const ulonglong2*)(Xs + s);
        ulonglong2 xa1 = *(const ulonglong2*)(Xs + s + 4);
        ulonglong2 xb0 = *(const ulonglong2*)(Xs + s + OFF14);
        ulonglong2 xb1 = *(const ulonglong2*)(Xs + s + OFF14 + 4);

        #pragma unroll 1
        for (int k4 = 0; k4 < 32; k4++){
            s += 8;
            // prefetch next iteration's X (padding covers last-iter overrun)
            ulonglong2 na0 = *(const ulonglong2*)(Xs + s);
            ulonglong2 na1 = *(const ulonglong2*)(Xs + s + 4);
            ulonglong2 nb0 = *(const ulonglong2*)(Xs + s + OFF14);
            ulonglong2 nb1 = *(const ulonglong2*)(Xs + s + OFF14 + 4);

            {
                ulonglong2 wv0 = wp[k4 + 0*128];
                ulonglong2 wv1 = wp[k4 + 1*128];
                ulonglong2 wv2 = wp[k4 + 2*128];
                ulonglong2 wv3 = wp[k4 + 3*128];
                FMA2(acc[0][0], wv0.x, xa0.x); FMA2(acc[0][1], wv0.x, xa0.y);
                FMA2(acc[0][2], wv0.x, xb0.x); FMA2(acc[0][3], wv0.x, xb0.y);
                FMA2(acc[0][0], wv0.y, xa1.x); FMA2(acc[0][1], wv0.y, xa1.y);
                FMA2(acc[0][2], wv0.y, xb1.x); FMA2(acc[0][3], wv0.y, xb1.y);
                FMA2(acc[1][0], wv1.x, xa0.x); FMA2(acc[1][1], wv1.x, xa0.y);
                FMA2(acc[1][2], wv1.x, xb0.x); FMA2(acc[1][3], wv1.x, xb0.y);
                FMA2(acc[1][0], wv1.y, xa1.x); FMA2(acc[1][1], wv1.y, xa1.y);
                FMA2(acc[1][2], wv1.y, xb1.x); FMA2(acc[1][3], wv1.y, xb1.y);
                FMA2(acc[2][0], wv2.x, xa0.x); FMA2(acc[2][1], wv2.x, xa0.y);
                FMA2(acc[2][2], wv2.x, xb0.x); FMA2(acc[2][3], wv2.x, xb0.y);
                FMA2(acc[2][0], wv2.y, xa1.x); FMA2(acc[2][1], wv2.y, xa1.y);
                FMA2(acc[2][2], wv2.y, xb1.x); FMA2(acc[2][3], wv2.y, xb1.y);
                FMA2(acc[3][0], wv3.x, xa0.x); FMA2(acc[3][1], wv3.x, xa0.y);
                FMA2(acc[3][2], wv3.x, xb0.x); FMA2(acc[3][3], wv3.x, xb0.y);
                FMA2(acc[3][0], wv3.y, xa1.x); FMA2(acc[3][1], wv3.y, xa1.y);
                FMA2(acc[3][2], wv3.y, xb1.x); FMA2(acc[3][3], wv3.y, xb1.y);
            }
            {
                ulonglong2 wv4 = wp[k4 + 4*128];
                ulonglong2 wv5 = wp[k4 + 5*128];
                ulonglong2 wv6 = wp[k4 + 6*128];
                ulonglong2 wv7 = wp[k4 + 7*128];
                FMA2(acc[4][0], wv4.x, xa0.x); FMA2(acc[4][1], wv4.x, xa0.y);
                FMA2(acc[4][2], wv4.x, xb0.x); FMA2(acc[4][3], wv4.x, xb0.y);
                FMA2(acc[4][0], wv4.y, xa1.x); FMA2(acc[4][1], wv4.y, xa1.y);
                FMA2(acc[4][2], wv4.y, xb1.x); FMA2(acc[4][3], wv4.y, xb1.y);
                FMA2(acc[5][0], wv5.x, xa0.x); FMA2(acc[5][1], wv5.x, xa0.y);
                FMA2(acc[5][2], wv5.x, xb0.x); FMA2(acc[5][3], wv5.x, xb0.y);
                FMA2(acc[5][0], wv5.y, xa1.x); FMA2(acc[5][1], wv5.y, xa1.y);
                FMA2(acc[5][2], wv5.y, xb1.x); FMA2(acc[5][3], wv5.y, xb1.y);
                FMA2(acc[6][0], wv6.x, xa0.x); FMA2(acc[6][1], wv6.x, xa0.y);
                FMA2(acc[6][2], wv6.x, xb0.x); FMA2(acc[6][3], wv6.x, xb0.y);
                FMA2(acc[6][0], wv6.y, xa1.x); FMA2(acc[6][1], wv6.y, xa1.y);
                FMA2(acc[6][2], wv6.y, xb1.x); FMA2(acc[6][3], wv6.y, xb1.y);
                FMA2(acc[7][0], wv7.x, xa0.x); FMA2(acc[7][1], wv7.x, xa0.y);
                FMA2(acc[7][2], wv7.x, xb0.x); FMA2(acc[7][3], wv7.x, xb0.y);
                FMA2(acc[7][0], wv7.y, xa1.x); FMA2(acc[7][1], wv7.y, xa1.y);
                FMA2(acc[7][2], wv7.y, xb1.x); FMA2(acc[7][3], wv7.y, xb1.y);
            }
            xa0 = na0; xa1 = na1; xb0 = nb0; xb1 = nb1;
        }
    }

    // ---- epilogue: all 4 quarters participate ----
    __syncthreads();                        // all GEMM reads of Xs done
    float* comb = Xs;                       // 4 buffers of [64][56]

    float sres[8][4];
    #pragma unroll
    for (int i = 0; i < 8; i++)
        #pragma unroll
        for (int j = 0; j < 4; j++){
            float2 f = up2(acc[i][j]);
            sres[i][j] = f.x + f.y;
        }

    {
        float* cb = comb + kq*NREG*TT;
        #pragma unroll
        for (int i = 0; i < 8; i++){
            int rw = (n0+i)*TT;
            *(float2*)&cb[rw + p0]      = make_float2(sres[i][0], sres[i][1]);
            *(float2*)&cb[rw + p0 + 28] = make_float2(sres[i][2], sres[i][3]);
        }
    }
    __syncthreads();

    // each thread owns rows ra = n0 + 2*kq, ra+1 for its 4 pixels
    int ra = n0 + 2*kq;
    float fa[4], fc[4];
    {
        float ba = wb[ra], bb = wb[ra+1];
        int rwa = ra*TT, rwb = rwa + TT;
        #pragma unroll
        for (int j = 0; j < 4; j++){
            int px = (j < 2) ? (p0 + j) : (p0 + 26 + j);   // p0,p0+1,p0+28,p0+29
            float sa = ba, sb = bb;
            #pragma unroll
            for (int q = 0; q < 4; q++){
                sa += comb[q*NREG*TT + rwa + px];
                sb += comb[q*NREG*TT + rwb + px];
            }
            fa[j] = sa; fc[j] = sb;
            pn[(tn*4 + kq)*TT + px] = sa*sa + sb*sb;
        }
    }
    __syncthreads();
    if (tid < TT){
        float ss = 0.f;
        #pragma unroll
        for (int g = 0; g < 32; g++) ss += pn[g*TT + tid];
        sinv[tid] = 1.0f / fmaxf(sqrtf(ss), 1e-12f);
    }
    __syncthreads();
    {
        float* outb = g_srean + ((size_t)b*NREG)*HW + hw0;
        float a0 = satt[p0], a1v = satt[p0+1], a2 = satt[p0+28], a3 = satt[p0+29];
        float i0 = sinv[p0], i1 = sinv[p0+1], i2 = sinv[p0+28], i3 = sinv[p0+29];

        float o0 = fa[0]*i0, o1 = fa[1]*i1, o2 = fa[2]*i2, o3 = fa[3]*i3;
        float* orow = outb + (size_t)ra*HW;
        stcs2(&orow[p0],      make_float2(o0, o1));
        stcs2(&orow[p0 + 28], make_float2(o2, o3));
        stile[ra*NTILE + tt] = o0*a0 + o1*a1v + o2*a2 + o3*a3;

        float q0 = fc[0]*i0, q1 = fc[1]*i1, q2 = fc[2]*i2, q3 = fc[3]*i3;
        float* orow2 = orow + HW;
        stcs2(&orow2[p0],      make_float2(q0, q1));
        stcs2(&orow2[p0 + 28], make_float2(q2, q3));
        stile[(ra+1)*NTILE + tt] = q0*a0 + q1*a1v + q2*a2 + q3*a3;
    }
    __syncthreads();
    if (tid < NREG){
        float q = 0.f;
        #pragma unroll
        for (int tl = 0; tl < NTILE; tl++) q += stile[tid*NTILE + tl];
        g_scorep[(b*NTILE + tile)*NREG + tid] = q;
    }
}

// ---------------- K5: feat partials, split-K x4 (round-8 proven) ----------------
#define FPAD 129
__global__ void k_feat(const float* __restrict__ fw){
    __shared__ float pooled[BB*FPAD];
    __shared__ float ws[8*FPAD];
    int tid = threadIdx.x;            // 256
    int o0  = (blockIdx.x & 63) * 8;
    int q   = blockIdx.x >> 6;        // 0..3
    int c0  = q * 128;

    for (int idx = tid; idx < BB*128; idx += 256){
        int bb = idx >> 7, kk = idx & 127;
        pooled[bb*FPAD + kk] = g_pooled[bb*CC + c0 + kk];
    }
    for (int idx = tid; idx < 8*128; idx += 256){
        int oo = idx >> 7, kk = idx & 127;
        ws[oo*FPAD + kk] = fw[(size_t)(o0+oo)*CC + c0 + kk];
    }
    __syncthreads();

    #pragma unroll
    for (int rr = 0; rr < 2; rr++){
        int p  = tid*2 + rr;
        int bb = p >> 3, oo = p & 7;
        float s = 0.f;
        #pragma unroll 4
        for (int k = 0; k < 128; k++) s = fmaf(pooled[bb*FPAD + k], ws[oo*FPAD + k], s);
        g_featp[(q*BB + bb)*CC + o0 + oo] = s;
    }
}

// ---------------- K6: loss (blocks 0..63) + dual_sim (blocks 64..127) ----------------
__global__ void k_lossdual(const float* __restrict__ fb, float* __restrict__ out){
    int tid = threadIdx.x;  // 256
    if (blockIdx.x < BB){
        int b = blockIdx.x;
        __shared__ float ssc[NREG];
        __shared__ int s_nmax;
        __shared__ float red[8];
        if (tid < NREG){
            float sv = 0.f;
            #pragma unroll
            for (int tl = 0; tl < NTILE; tl++) sv += g_scorep[(b*NTILE + tl)*NREG + tid];
            ssc[tid] = sv;
        }
        __syncthreads();
        if (tid == 0){
            float m = 0.f;
            for (int n = 0; n < NREG; n++) m += ssc[n];
            m *= (1.0f/NREG);
            float bmax = ssc[0]; int imax = 0;
            float sp = 0.f, sq = 0.f;
            for (int n = 0; n < NREG; n++){
                float x = ssc[n];
                if (x > bmax){ bmax = x; imax = n; }
                if (x > m) sp += x; else sq += x;
            }
            sp *= (1.0f/NREG); sq *= (1.0f/NREG);
            float d = sq - sp;
            g_l3[b] = (d > 20.0f) ? d : log1pf(expf(d));
            s_nmax = imax;
        }
        __syncthreads();

        const float* pl = g_att2 + b*HW;
        const float* ql = g_srean + ((size_t)b*NREG + s_nmax)*HW;
        const float qs = 1.0f/(float)NREG;

        float mp = -1e30f, mq = -1e30f;
        for (int h = tid; h < HW; h += 256){
            mp = fmaxf(mp, pl[h]);
            mq = fmaxf(mq, ql[h]*qs);
        }
        mp = blockRedMax256(mp, red);
        mq = blockRedMax256(mq, red);

        float ep = 0.f, eq = 0.f;
        for (int h = tid; h < HW; h += 256){
            ep += expf(pl[h] - mp);
            eq += expf(ql[h]*qs - mq);
        }
        ep = blockRedSum256(ep, red);
        eq = blockRedSum256(eq, red);
        float lsep = mp + logf(ep);
        float lseq = mq + logf(eq);

        float S = 0.f;
        for (int h = tid; h < HW; h += 256){
            float lp = pl[h] - lsep;
            float lq = ql[h]*qs - lseq;
            float p  = expf(lp);
            float q  = expf(lq);
            float lm = logf(0.5f*(p + q));
            S += p*(lp - lm) + q*(lq - lm);
        }
        S = blockRedSum256(S, red);
        if (tid == 0) g_ls[b] = S;
    } else {
        int b = blockIdx.x - BB;
        __shared__ float fr[CC];
        __shared__ float red[8];
        __shared__ float sinvb;
        float ss = 0.f;
        for (int c = tid; c < CC; c += 256){
            float x = g_featp[b*CC + c] + g_featp[(BB + b)*CC + c]
                    + g_featp[(2*BB + b)*CC + c] + g_featp[(3*BB + b)*CC + c] + fb[c];
            fr[c] = x; ss += x*x;
        }
        ss = blockRedSum256(ss, red);
        if (tid == 0) sinvb = 1.0f / fmaxf(sqrtf(ss), 1e-12f);
        __syncthreads();
        int warp = tid >> 5, lane = tid & 31;
        for (int j = warp; j < BB; j += 8){
            const float* a = g_a1 + j*CC;
            float s = 0.f;
            for (int c = lane; c < CC; c += 32) s += fr[c] * a[c];
            s = wredsum(s);
            if (lane == 0) out[b*BB + j] = s * sinvb;
        }
    }
}

// ---------------- K8: final scalar ----------------
__global__ void k_final(float* __restrict__ out, int li){
    int t = threadIdx.x;  // 64
    __shared__ float r3[BB], rls[BB];
    r3[t] = g_l3[t]; rls[t] = g_ls[t];
    __syncthreads();
    if (t == 0){
        float a = 0.f, c2 = 0.f;
        for (int i = 0; i < BB; i++){ a += r3[i]; c2 += rls[i]; }
        float loss3 = a / (float)BB;
        float loss2 = 0.5f * c2 / (float)BB;
        out[li] = 0.1f*loss3 + 0.1f*loss2;
    }
}

// ---------------- launcher ----------------
extern "C" void kernel_launch(void* const* d_in, const int* in_sizes, int n_in,
                              void* d_out, int out_size){
    const float* v     = (const float*)d_in[0];
    const float* t     = (const float*)d_in[1];
    const float* cw    = (const float*)d_in[2];
    const float* cb    = (const float*)d_in[3];
    const float* gamma = (const float*)d_in[4];
    const float* beta  = (const float*)d_in[5];
    const float* fw    = (const float*)d_in[6];
    const float* fb    = (const float*)d_in[7];
    float* out = (float*)d_out;

    cudaFuncSetAttribute(k_main, cudaFuncAttributeMaxDynamicSharedMemorySize, XS_BYTES);

    k_rowsum<<<(BB*CC)/8, 256>>>(v);
    k_prep<<<CC + BB, 128>>>(gamma, beta, t);
    k_main<<<BB*NTILE, GT, XS_BYTES>>>(v, cw, cb);
    k_feat<<<256, 256>>>(fw);
    k_lossdual<<<2*BB, 256>>>(fb, out);
    int li = (out_size > 4096) ? 4096 : (out_size - 1);
    k_final<<<1, 64>>>(out, li);
}